// round 13
// baseline (speedup 1.0000x reference)
#include <cuda_runtime.h>
#include <cstdint>

#define NPROP 36864     // 64*64*9 proposals
#define NTOP  6000      // PRE_NMS_TOPN
#define NW    94        // ceil(6000/64) suppression words per row
#define NOUT  300       // POST_NMS_TOPN
#define NBIN  2048
#define NCAND 8192
#define NBLK  148
#define NTHR  1024
#define NSUB  (NTHR / 64)               // 16 mask sub-tiles per block
#define CHW   8                         // words per scan chunk (512 boxes)
#define NCHUNK ((NW + CHW - 1) / CHW)   // 12
#define DIAGSZ (CHW * 64 * CHW)         // 4096 u64 = 32 KB per buffer

// ---------------- global scratch (zero-initialized at module load) ----------
__device__ float4             g_boxes[NPROP];
__device__ unsigned long long g_keys[NPROP];
__device__ unsigned           g_hist[NBIN];      // zeroed after use each run
__device__ unsigned           g_binfill[NBIN];   // zeroed after use each run
__device__ unsigned long long g_cand[NCAND];
__device__ unsigned long long g_sorted[NCAND];
__device__ float4             g_tbox[NTOP];
__device__ float              g_tarea[NTOP];
__device__ unsigned           g_validbits32[2 * NW];
__device__ unsigned long long g_mask[(size_t)NTOP * NW];   // 4.5 MB (upper tri)
__device__ unsigned           g_bar_cnt;
__device__ unsigned           g_bar_gen;          // monotone across replays

__constant__ float c_ax1[9] = {-84.f,-176.f,-360.f,-56.f,-120.f,-248.f,-36.f,-80.f,-168.f};
__constant__ float c_ay1[9] = {-40.f,-88.f,-184.f,-56.f,-120.f,-248.f,-80.f,-168.f,-344.f};
__constant__ float c_aw[9]  = {184.f,368.f,736.f,128.f,256.f,512.f,88.f,176.f,352.f};
__constant__ float c_ah[9]  = {96.f,192.f,384.f,128.f,256.f,512.f,176.f,352.f,704.f};

__device__ __forceinline__ int score_bin(float s) {
    int b = (int)__fmul_rn(s, 2048.0f);
    return b > 2047 ? 2047 : (b < 0 ? 0 : b);
}

// generational grid barrier: load-spin (no RMW polling)
__device__ __forceinline__ void gridbar() {
    __syncthreads();
    if (threadIdx.x == 0) {
        __threadfence();
        unsigned g = *((volatile unsigned*)&g_bar_gen);   // read BEFORE arrive
        if (atomicAdd(&g_bar_cnt, 1u) == NBLK - 1) {
            atomicExch(&g_bar_cnt, 0u);
            __threadfence();
            atomicAdd(&g_bar_gen, 1u);                    // release
        } else {
            while (*((volatile unsigned*)&g_bar_gen) == g) { }
        }
        __threadfence();
    }
    __syncthreads();
}

struct SmemP2 { unsigned s[NBIN]; unsigned shist[NBIN]; };   // binstart, hist
struct SmemP5 { float4 cboxs[NSUB * 64]; float careas[NSUB * 64]; };
union  SmemU  { SmemP2 p2; SmemP5 p5; };

__global__ void __launch_bounds__(NTHR, 1)
fused_kernel(const float* __restrict__ scores,
             const float* __restrict__ deltas,
             float* __restrict__ out) {
    extern __shared__ unsigned long long diagbuf[];   // 2 * DIAGSZ u64 (64 KB)
    __shared__ SmemU u;
    __shared__ unsigned wsum[32], wsuf[32];
    __shared__ int scut, sncand;
    __shared__ unsigned long long vbits[NW];
    __shared__ unsigned long long remv8[CHW];   // remv of current chunk
    __shared__ unsigned long long nrem8[CHW];   // remv being built for next
    __shared__ short kept[NOUT];
    __shared__ int cnt;

    const int t    = threadIdx.x;
    const int gid  = blockIdx.x * NTHR + t;
    const int lane = t & 31;
    const int wid  = t >> 5;

    // ================= phase 1: decode + keys + histogram ===================
    if (gid < NPROP) {
        int a   = gid % 9;
        int pos = gid / 9;
        int wx  = pos % 64;
        int hy  = pos / 64;
        float sx = (float)(wx * 16);
        float sy = (float)(hy * 16);

        const float* d = deltas + (size_t)pos * 36 + a * 4;
        float dx = d[0], dy = d[1], dw = d[2], dh = d[3];
        float score = scores[(size_t)pos * 18 + 9 + a];

        float aw = c_aw[a], ah = c_ah[a];
        float acx = __fadd_rn(__fadd_rn(c_ax1[a], sx), __fmul_rn(0.5f, aw));
        float acy = __fadd_rn(__fadd_rn(c_ay1[a], sy), __fmul_rn(0.5f, ah));

        float pcx = __fadd_rn(__fmul_rn(dx, aw), acx);
        float pcy = __fadd_rn(__fmul_rn(dy, ah), acy);
        float pw  = __fmul_rn(expf(dw), aw);
        float ph  = __fmul_rn(expf(dh), ah);

        float x1 = fminf(fmaxf(__fsub_rn(pcx, __fmul_rn(0.5f, pw)), 0.f), 1023.f);
        float y1 = fminf(fmaxf(__fsub_rn(pcy, __fmul_rn(0.5f, ph)), 0.f), 1023.f);
        float x2 = fminf(fmaxf(__fadd_rn(pcx, __fmul_rn(0.5f, pw)), 0.f), 1023.f);
        float y2 = fminf(fmaxf(__fadd_rn(pcy, __fmul_rn(0.5f, ph)), 0.f), 1023.f);

        float ws = __fadd_rn(__fsub_rn(x2, x1), 1.f);
        float hs = __fadd_rn(__fsub_rn(y2, y1), 1.f);
        bool valid = (ws >= 16.f) && (hs >= 16.f);

        g_boxes[gid] = make_float4(x1, y1, x2, y2);
        unsigned fk = valid ? (__float_as_uint(score) ^ 0x80000000u) : 0x007FFFFFu;
        g_keys[gid] = ((unsigned long long)(~fk) << 32) | (unsigned)gid;
        if (valid) atomicAdd(&g_hist[score_bin(score)], 1u);
    }
    gridbar();

    // ===== phase 2: warp-shuffle suffix sum over bins + cut, then scatter ====
    {
        unsigned h0 = g_hist[2 * t], h1 = g_hist[2 * t + 1];
        unsigned v = h0 + h1;
        unsigned x = v;
        #pragma unroll
        for (int d = 1; d < 32; d <<= 1) {
            unsigned y = __shfl_down_sync(0xFFFFFFFFu, x, d);
            if (lane + d < 32) x += y;
        }
        if (lane == 0) wsum[wid] = x;
        __syncthreads();
        if (wid == 0) {
            unsigned wx = wsum[lane];
            #pragma unroll
            for (int d = 1; d < 32; d <<= 1) {
                unsigned y = __shfl_down_sync(0xFFFFFFFFu, wx, d);
                if (lane + d < 32) wx += y;
            }
            wsuf[lane] = wx;
        }
        __syncthreads();
        unsigned S = x + ((wid < 31) ? wsuf[wid + 1] : 0u);   // s[2t]
        unsigned total  = wsuf[0];
        unsigned target = total < NTOP ? total : (unsigned)NTOP;
        unsigned s_even = S;
        unsigned s_odd  = S - h0;       // s[2t+1]
        unsigned s_nxt  = S - v;        // s[2t+2]
        u.p2.shist[2 * t]     = h0;
        u.p2.shist[2 * t + 1] = h1;
        u.p2.s[2 * t]     = S - h0;     // binstart even
        u.p2.s[2 * t + 1] = S - v;      // binstart odd
        if (total > 0) {
            if (s_even >= target && s_odd < target) {
                scut = 2 * t;
                sncand = (int)(s_even < NCAND ? s_even : NCAND);
            }
            if (s_odd >= target && (2 * t + 1 == NBIN - 1 || s_nxt < target)) {
                scut = 2 * t + 1;
                sncand = (int)(s_odd < NCAND ? s_odd : NCAND);
            }
        } else if (t == 0) { scut = NBIN; sncand = 0; }
    }
    __syncthreads();
    if (gid < NPROP) {                            // scatter
        unsigned long long key = g_keys[gid];
        unsigned hk = (unsigned)(key >> 32);
        if (hk != 0xFF800000u) {
            float score = __uint_as_float(~hk ^ 0x80000000u);
            int b = score_bin(score);
            if (b >= scut) {
                unsigned pos = u.p2.s[b] + atomicAdd(&g_binfill[b], 1u);
                if (pos < NCAND) g_cand[pos] = key;
            }
        }
    }
    gridbar();

    // ================= phase 3: exact in-bin rank (+ zero binfill) ==========
    if (gid < NBIN) g_binfill[gid] = 0u;
    if (gid < sncand) {
        unsigned long long key = g_cand[gid];
        unsigned hk = (unsigned)(key >> 32);
        float score = __uint_as_float(~hk ^ 0x80000000u);
        int b = score_bin(score);
        unsigned seg0 = u.p2.s[b];
        unsigned segn = u.p2.shist[b];
        if (seg0 + segn > NCAND) segn = NCAND - seg0;
        unsigned r = 0;
        for (unsigned q = 0; q < segn; q++)
            r += (g_cand[seg0 + q] < key) ? 1u : 0u;
        unsigned rank = seg0 + r;
        if (rank < NCAND) g_sorted[rank] = key;
    }
    gridbar();

    // ============ phase 4: gather top-6000 + validbits (+ zero hist) ========
    if (gid < NBIN) g_hist[gid] = 0u;
    if (gid < NW * 64) {
        bool valid = false;
        float4 bx = make_float4(0.f, 0.f, 0.f, 0.f);
        if (gid < NTOP && gid < sncand) {
            unsigned long long key = g_sorted[gid];
            bx = g_boxes[(unsigned)key];
            valid = true;
        }
        unsigned bal = __ballot_sync(0xFFFFFFFFu, valid);
        if ((t & 31) == 0) g_validbits32[gid >> 5] = bal;
        if (gid < NTOP) {
            g_tbox[gid]  = bx;
            g_tarea[gid] = __fmul_rn(__fadd_rn(__fsub_rn(bx.z, bx.x), 1.f),
                                     __fadd_rn(__fsub_rn(bx.w, bx.y), 1.f));
        }
    }
    gridbar();

    // ================= phase 5: NMS mask (div-free, tiled) ==================
    {
        const int sub = t >> 6, row = t & 63;
        const int ntiles = NW * NW;
        const int stride = NBLK * NSUB;
        const int iters = (ntiles + stride - 1) / stride;
        for (int it = 0; it < iters; it++) {
            int tile = blockIdx.x * NSUB + sub + it * stride;
            int rb = tile / NW, cb = tile - rb * NW;
            bool act = (tile < ntiles) && (cb >= rb);
            __syncthreads();
            if (act) {
                int j = cb * 64 + row;
                if (j < NTOP) {
                    u.p5.cboxs[sub * 64 + row]  = g_tbox[j];
                    u.p5.careas[sub * 64 + row] = g_tarea[j];
                } else {
                    u.p5.cboxs[sub * 64 + row]  = make_float4(0.f, 0.f, 0.f, 0.f);
                    u.p5.careas[sub * 64 + row] = 0.f;
                }
            }
            __syncthreads();
            if (act) {
                int i = rb * 64 + row;
                if (i < NTOP) {
                    float4 r = g_tbox[i];
                    float  ra = g_tarea[i];
                    int j0 = cb * 64;
                    int jmax = min(64, NTOP - j0);
                    unsigned long long bits = 0;
                    #pragma unroll 4
                    for (int jj = 0; jj < jmax; jj++) {
                        int j = j0 + jj;
                        if (j <= i) continue;
                        float4 c = u.p5.cboxs[sub * 64 + jj];
                        float xx1 = fmaxf(r.x, c.x);
                        float yy1 = fmaxf(r.y, c.y);
                        float xx2 = fminf(r.z, c.z);
                        float yy2 = fminf(r.w, c.w);
                        float iw = fmaxf(__fadd_rn(__fsub_rn(xx2, xx1), 1.f), 0.f);
                        float ih = fmaxf(__fadd_rn(__fsub_rn(yy2, yy1), 1.f), 0.f);
                        float inter = __fmul_rn(iw, ih);
                        float denom = __fsub_rn(__fadd_rn(ra, u.p5.careas[sub * 64 + jj]), inter);
                        if (inter > __fmul_rn(0.5f, denom)) bits |= 1ULL << jj;
                    }
                    g_mask[(size_t)i * NW + cb] = bits;
                }
            }
        }
    }
    gridbar();

    // ===== phase 6: chunked greedy scan (block 0), lazy 8-word remv ==========
    if (blockIdx.x != 0) return;

    for (int w = t; w < NW; w += NTHR)
        vbits[w] = ((unsigned long long)g_validbits32[2 * w + 1] << 32) |
                   g_validbits32[2 * w];
    if (t < CHW) remv8[t] = 0ULL;
    if (t == 0) cnt = 0;
    __syncthreads();

    // prefetch chunk 0 into buffer 0 (all threads)
    {
        const int nw0 = (NW < CHW) ? NW : CHW;
        for (int idx = t; idx < nw0 * 64 * CHW; idx += NTHR) {
            int rr = idx / CHW, k = idx - rr * CHW;
            diagbuf[idx] = (k < nw0) ? g_mask[(size_t)rr * NW + k] : 0ULL;
        }
    }
    __syncthreads();

    for (int ch = 0; ch < NCHUNK; ch++) {
        const int w0 = ch * CHW;
        const int nw = (NW - w0 < CHW) ? (NW - w0) : CHW;
        unsigned long long* buf = diagbuf + (ch & 1) * DIAGSZ;

        if (t == 0) {
            // serial greedy pass on this chunk (all data in smem/regs)
            unsigned long long r[CHW];
            #pragma unroll
            for (int k = 0; k < CHW; k++) r[k] = (k < nw) ? remv8[k] : ~0ULL;
            int c = cnt;
            for (int k = 0; k < nw && c < NOUT; k++) {
                unsigned long long avail = ~r[k] & vbits[w0 + k];
                while (avail) {
                    int b = __ffsll((long long)avail) - 1;
                    kept[c++] = (short)((w0 + k) * 64 + b);
                    if (c == NOUT) break;
                    int rr = k * 64 + b;
                    #pragma unroll
                    for (int k2 = 0; k2 < CHW; k2++)
                        if (k2 >= k) r[k2] |= buf[rr * CHW + k2];
                    unsigned long long gt = (b == 63) ? 0ULL : (~0ULL << (b + 1));
                    avail = ~r[k] & vbits[w0 + k] & gt;
                }
            }
            cnt = c;
        } else if (t >= 512 && ch + 1 < NCHUNK) {
            // concurrently prefetch next chunk's diagonal block
            const int w0n = (ch + 1) * CHW;
            const int nwn = (NW - w0n < CHW) ? (NW - w0n) : CHW;
            unsigned long long* nbuf = diagbuf + ((ch + 1) & 1) * DIAGSZ;
            for (int idx = t - 512; idx < nwn * 64 * CHW; idx += 512) {
                int rr = idx / CHW, k = idx - rr * CHW;
                int gi = w0n * 64 + rr;
                nbuf[idx] = (k < nwn && gi < NTOP)
                          ? g_mask[(size_t)gi * NW + w0n + k] : 0ULL;
            }
        }
        __syncthreads();
        if (cnt >= NOUT || w0 + nw >= NW) break;

        // rebuild remv for the NEXT chunk's 8 words from ALL keeps so far
        if (t < CHW) nrem8[t] = 0ULL;
        __syncthreads();
        {
            int w = t & (CHW - 1);
            int gw = (ch + 1) * CHW + w;
            if (gw < NW) {
                unsigned long long acc = 0;
                for (int q = t >> 3; q < cnt; q += NTHR / CHW)
                    acc |= g_mask[(size_t)kept[q] * NW + gw];
                if (acc) atomicOr(&nrem8[w], acc);
            }
        }
        __syncthreads();
        if (t < CHW) remv8[t] = nrem8[t];
        __syncthreads();
    }
    __syncthreads();

    int c = cnt;
    const float inv = 0.0009765625f;   // 1/1024
    for (int o = t; o < NOUT; o += NTHR) {
        float4 bo = make_float4(0.f, 0.f, 0.f, 0.f);
        if (o < c) {
            float4 bb = g_tbox[kept[o]];
            bo.x = bb.x * inv; bo.y = bb.y * inv;
            bo.z = bb.z * inv; bo.w = bb.w * inv;
        }
        out[o * 4 + 0] = bo.x;
        out[o * 4 + 1] = bo.y;
        out[o * 4 + 2] = bo.z;
        out[o * 4 + 3] = bo.w;
    }
}

// ---------------- launch ------------------------------------------------------
extern "C" void kernel_launch(void* const* d_in, const int* in_sizes, int n_in,
                              void* d_out, int out_size) {
    const float* scores = (const float*)d_in[0];
    const float* deltas = (const float*)d_in[1];
    if (in_sizes[0] != 73728) {
        scores = (const float*)d_in[1];
        deltas = (const float*)d_in[0];
    }
    float* out = (float*)d_out;

    static bool attr_set = false;
    if (!attr_set) {
        cudaFuncSetAttribute(fused_kernel,
                             cudaFuncAttributeMaxDynamicSharedMemorySize,
                             2 * DIAGSZ * sizeof(unsigned long long));
        attr_set = true;
    }

    fused_kernel<<<NBLK, NTHR, 2 * DIAGSZ * sizeof(unsigned long long)>>>(
        scores, deltas, out);
}

// round 14
// speedup vs baseline: 1.0244x; 1.0244x over previous
#include <cuda_runtime.h>
#include <cstdint>

#define NPROP 36864     // 64*64*9 proposals
#define NTOP  6000      // PRE_NMS_TOPN
#define NW    94        // ceil(6000/64) suppression words per row
#define NOUT  300       // POST_NMS_TOPN
#define NBIN  2048
#define NCAND 8192
#define NBLK  148
#define NTHR  1024
#define NSUB  (NTHR / 64)               // 16 mask sub-tiles per block
#define CHW   8                         // words per scan chunk (512 boxes)
#define NCHUNK ((NW + CHW - 1) / CHW)   // 12
#define DIAGSZ (CHW * 64 * CHW)         // 4096 u64 = 32 KB per buffer

// ---------------- global scratch (zero-initialized at module load) ----------
__device__ float4             g_boxes[NPROP];
__device__ unsigned long long g_keys[NPROP];
__device__ unsigned           g_hist[NBIN];      // zeroed after use each run
__device__ unsigned           g_binfill[NBIN];   // zeroed after use each run
__device__ unsigned long long g_cand[NCAND];
__device__ unsigned long long g_sorted[NCAND];
__device__ float4             g_tbox[NTOP];
__device__ float              g_tarea[NTOP];
__device__ unsigned           g_validbits32[2 * NW];
__device__ unsigned long long g_mask[(size_t)NTOP * NW];   // 4.5 MB (upper tri)
__device__ unsigned           g_bar_cnt;
__device__ unsigned           g_bar_gen;          // monotone across replays

__constant__ float c_ax1[9] = {-84.f,-176.f,-360.f,-56.f,-120.f,-248.f,-36.f,-80.f,-168.f};
__constant__ float c_ay1[9] = {-40.f,-88.f,-184.f,-56.f,-120.f,-248.f,-80.f,-168.f,-344.f};
__constant__ float c_aw[9]  = {184.f,368.f,736.f,128.f,256.f,512.f,88.f,176.f,352.f};
__constant__ float c_ah[9]  = {96.f,192.f,384.f,128.f,256.f,512.f,176.f,352.f,704.f};

__device__ __forceinline__ int score_bin(float s) {
    int b = (int)__fmul_rn(s, 2048.0f);
    return b > 2047 ? 2047 : (b < 0 ? 0 : b);
}

// generational grid barrier: load-spin (no RMW polling)
__device__ __forceinline__ void gridbar() {
    __syncthreads();
    if (threadIdx.x == 0) {
        __threadfence();
        unsigned g = *((volatile unsigned*)&g_bar_gen);   // read BEFORE arrive
        if (atomicAdd(&g_bar_cnt, 1u) == NBLK - 1) {
            atomicExch(&g_bar_cnt, 0u);
            __threadfence();
            atomicAdd(&g_bar_gen, 1u);                    // release
        } else {
            while (*((volatile unsigned*)&g_bar_gen) == g) { }
        }
        __threadfence();
    }
    __syncthreads();
}

struct SmemP2 { unsigned s[NBIN]; unsigned shist[NBIN]; };   // binstart, hist
struct SmemP5 { float4 cboxs[NSUB * 64]; float careas[NSUB * 64]; };
union  SmemU  { SmemP2 p2; SmemP5 p5; };

__global__ void __launch_bounds__(NTHR, 1)
fused_kernel(const float* __restrict__ scores,
             const float* __restrict__ deltas,
             float* __restrict__ out) {
    extern __shared__ unsigned long long diagbuf[];   // 2 * DIAGSZ u64 (64 KB)
    __shared__ SmemU u;
    __shared__ unsigned wsum[32], wsuf[32];
    __shared__ int scut, sncand;
    __shared__ unsigned long long vbits[NW];
    __shared__ unsigned long long remv8[CHW];   // remv of current chunk
    __shared__ unsigned long long nrem8[CHW];   // remv being built for next
    __shared__ short kept[NOUT];
    __shared__ int cnt;

    const int t    = threadIdx.x;
    const int gid  = blockIdx.x * NTHR + t;
    const int lane = t & 31;
    const int wid  = t >> 5;

    // ================= phase 1: decode + keys + histogram ===================
    if (gid < NPROP) {
        int a   = gid % 9;
        int pos = gid / 9;
        int wx  = pos % 64;
        int hy  = pos / 64;
        float sx = (float)(wx * 16);
        float sy = (float)(hy * 16);

        const float* d = deltas + (size_t)pos * 36 + a * 4;
        float dx = d[0], dy = d[1], dw = d[2], dh = d[3];
        float score = scores[(size_t)pos * 18 + 9 + a];

        float aw = c_aw[a], ah = c_ah[a];
        float acx = __fadd_rn(__fadd_rn(c_ax1[a], sx), __fmul_rn(0.5f, aw));
        float acy = __fadd_rn(__fadd_rn(c_ay1[a], sy), __fmul_rn(0.5f, ah));

        float pcx = __fadd_rn(__fmul_rn(dx, aw), acx);
        float pcy = __fadd_rn(__fmul_rn(dy, ah), acy);
        float pw  = __fmul_rn(expf(dw), aw);
        float ph  = __fmul_rn(expf(dh), ah);

        float x1 = fminf(fmaxf(__fsub_rn(pcx, __fmul_rn(0.5f, pw)), 0.f), 1023.f);
        float y1 = fminf(fmaxf(__fsub_rn(pcy, __fmul_rn(0.5f, ph)), 0.f), 1023.f);
        float x2 = fminf(fmaxf(__fadd_rn(pcx, __fmul_rn(0.5f, pw)), 0.f), 1023.f);
        float y2 = fminf(fmaxf(__fadd_rn(pcy, __fmul_rn(0.5f, ph)), 0.f), 1023.f);

        float ws = __fadd_rn(__fsub_rn(x2, x1), 1.f);
        float hs = __fadd_rn(__fsub_rn(y2, y1), 1.f);
        bool valid = (ws >= 16.f) && (hs >= 16.f);

        g_boxes[gid] = make_float4(x1, y1, x2, y2);
        unsigned fk = valid ? (__float_as_uint(score) ^ 0x80000000u) : 0x007FFFFFu;
        g_keys[gid] = ((unsigned long long)(~fk) << 32) | (unsigned)gid;
        if (valid) atomicAdd(&g_hist[score_bin(score)], 1u);
    }
    gridbar();

    // ===== phase 2: warp-shuffle suffix sum over bins + cut, then scatter ====
    {
        unsigned h0 = g_hist[2 * t], h1 = g_hist[2 * t + 1];
        unsigned v = h0 + h1;
        unsigned x = v;
        #pragma unroll
        for (int d = 1; d < 32; d <<= 1) {
            unsigned y = __shfl_down_sync(0xFFFFFFFFu, x, d);
            if (lane + d < 32) x += y;
        }
        if (lane == 0) wsum[wid] = x;
        __syncthreads();
        if (wid == 0) {
            unsigned wx = wsum[lane];
            #pragma unroll
            for (int d = 1; d < 32; d <<= 1) {
                unsigned y = __shfl_down_sync(0xFFFFFFFFu, wx, d);
                if (lane + d < 32) wx += y;
            }
            wsuf[lane] = wx;
        }
        __syncthreads();
        unsigned S = x + ((wid < 31) ? wsuf[wid + 1] : 0u);   // s[2t]
        unsigned total  = wsuf[0];
        unsigned target = total < NTOP ? total : (unsigned)NTOP;
        unsigned s_even = S;
        unsigned s_odd  = S - h0;       // s[2t+1]
        unsigned s_nxt  = S - v;        // s[2t+2]
        u.p2.shist[2 * t]     = h0;
        u.p2.shist[2 * t + 1] = h1;
        u.p2.s[2 * t]     = S - h0;     // binstart even
        u.p2.s[2 * t + 1] = S - v;      // binstart odd
        if (total > 0) {
            if (s_even >= target && s_odd < target) {
                scut = 2 * t;
                sncand = (int)(s_even < NCAND ? s_even : NCAND);
            }
            if (s_odd >= target && (2 * t + 1 == NBIN - 1 || s_nxt < target)) {
                scut = 2 * t + 1;
                sncand = (int)(s_odd < NCAND ? s_odd : NCAND);
            }
        } else if (t == 0) { scut = NBIN; sncand = 0; }
    }
    __syncthreads();
    if (gid < NPROP) {                            // scatter
        unsigned long long key = g_keys[gid];
        unsigned hk = (unsigned)(key >> 32);
        if (hk != 0xFF800000u) {
            float score = __uint_as_float(~hk ^ 0x80000000u);
            int b = score_bin(score);
            if (b >= scut) {
                unsigned pos = u.p2.s[b] + atomicAdd(&g_binfill[b], 1u);
                if (pos < NCAND) g_cand[pos] = key;
            }
        }
    }
    gridbar();

    // ================= phase 3: exact in-bin rank (+ zero binfill) ==========
    if (gid < NBIN) g_binfill[gid] = 0u;
    if (gid < sncand) {
        unsigned long long key = g_cand[gid];
        unsigned hk = (unsigned)(key >> 32);
        float score = __uint_as_float(~hk ^ 0x80000000u);
        int b = score_bin(score);
        unsigned seg0 = u.p2.s[b];
        unsigned segn = u.p2.shist[b];
        if (seg0 + segn > NCAND) segn = NCAND - seg0;
        unsigned r = 0;
        for (unsigned q = 0; q < segn; q++)
            r += (g_cand[seg0 + q] < key) ? 1u : 0u;
        unsigned rank = seg0 + r;
        if (rank < NCAND) g_sorted[rank] = key;
    }
    gridbar();

    // ============ phase 4: gather top-6000 + validbits (+ zero hist) ========
    if (gid < NBIN) g_hist[gid] = 0u;
    if (gid < NW * 64) {
        bool valid = false;
        float4 bx = make_float4(0.f, 0.f, 0.f, 0.f);
        if (gid < NTOP && gid < sncand) {
            unsigned long long key = g_sorted[gid];
            bx = g_boxes[(unsigned)key];
            valid = true;
        }
        unsigned bal = __ballot_sync(0xFFFFFFFFu, valid);
        if ((t & 31) == 0) g_validbits32[gid >> 5] = bal;
        if (gid < NTOP) {
            g_tbox[gid]  = bx;
            g_tarea[gid] = __fmul_rn(__fadd_rn(__fsub_rn(bx.z, bx.x), 1.f),
                                     __fadd_rn(__fsub_rn(bx.w, bx.y), 1.f));
        }
    }
    gridbar();

    // ================= phase 5: NMS mask (div-free, tiled) ==================
    {
        const int sub = t >> 6, row = t & 63;
        const int ntiles = NW * NW;
        const int stride = NBLK * NSUB;
        const int iters = (ntiles + stride - 1) / stride;
        for (int it = 0; it < iters; it++) {
            int tile = blockIdx.x * NSUB + sub + it * stride;
            int rb = tile / NW, cb = tile - rb * NW;
            bool act = (tile < ntiles) && (cb >= rb);
            __syncthreads();
            if (act) {
                int j = cb * 64 + row;
                if (j < NTOP) {
                    u.p5.cboxs[sub * 64 + row]  = g_tbox[j];
                    u.p5.careas[sub * 64 + row] = g_tarea[j];
                } else {
                    u.p5.cboxs[sub * 64 + row]  = make_float4(0.f, 0.f, 0.f, 0.f);
                    u.p5.careas[sub * 64 + row] = 0.f;
                }
            }
            __syncthreads();
            if (act) {
                int i = rb * 64 + row;
                if (i < NTOP) {
                    float4 r = g_tbox[i];
                    float  ra = g_tarea[i];
                    int j0 = cb * 64;
                    int jmax = min(64, NTOP - j0);
                    unsigned long long bits = 0;
                    #pragma unroll 4
                    for (int jj = 0; jj < jmax; jj++) {
                        int j = j0 + jj;
                        if (j <= i) continue;
                        float4 c = u.p5.cboxs[sub * 64 + jj];
                        float xx1 = fmaxf(r.x, c.x);
                        float yy1 = fmaxf(r.y, c.y);
                        float xx2 = fminf(r.z, c.z);
                        float yy2 = fminf(r.w, c.w);
                        float iw = fmaxf(__fadd_rn(__fsub_rn(xx2, xx1), 1.f), 0.f);
                        float ih = fmaxf(__fadd_rn(__fsub_rn(yy2, yy1), 1.f), 0.f);
                        float inter = __fmul_rn(iw, ih);
                        float denom = __fsub_rn(__fadd_rn(ra, u.p5.careas[sub * 64 + jj]), inter);
                        if (inter > __fmul_rn(0.5f, denom)) bits |= 1ULL << jj;
                    }
                    g_mask[(size_t)i * NW + cb] = bits;
                }
            }
        }
    }
    gridbar();

    // ===== phase 6: chunked greedy scan (block 0), lazy 8-word remv ==========
    if (blockIdx.x != 0) return;

    for (int w = t; w < NW; w += NTHR)
        vbits[w] = ((unsigned long long)g_validbits32[2 * w + 1] << 32) |
                   g_validbits32[2 * w];
    if (t < CHW) remv8[t] = 0ULL;
    if (t == 0) cnt = 0;
    __syncthreads();

    // prefetch chunk 0 into buffer 0 (all threads)
    {
        const int nw0 = (NW < CHW) ? NW : CHW;
        for (int idx = t; idx < nw0 * 64 * CHW; idx += NTHR) {
            int rr = idx / CHW, k = idx - rr * CHW;
            diagbuf[idx] = (k < nw0) ? g_mask[(size_t)rr * NW + k] : 0ULL;
        }
    }
    __syncthreads();

    for (int ch = 0; ch < NCHUNK; ch++) {
        const int w0 = ch * CHW;
        const int nw = (NW - w0 < CHW) ? (NW - w0) : CHW;
        unsigned long long* buf = diagbuf + (ch & 1) * DIAGSZ;

        if (t == 0) {
            // serial greedy pass on this chunk (all data in smem/regs)
            unsigned long long r[CHW];
            #pragma unroll
            for (int k = 0; k < CHW; k++) r[k] = (k < nw) ? remv8[k] : ~0ULL;
            int c = cnt;
            for (int k = 0; k < nw && c < NOUT; k++) {
                unsigned long long avail = ~r[k] & vbits[w0 + k];
                while (avail) {
                    int b = __ffsll((long long)avail) - 1;
                    kept[c++] = (short)((w0 + k) * 64 + b);
                    if (c == NOUT) break;
                    int rr = k * 64 + b;
                    #pragma unroll
                    for (int k2 = 0; k2 < CHW; k2++)
                        if (k2 >= k) r[k2] |= buf[rr * CHW + k2];
                    unsigned long long gt = (b == 63) ? 0ULL : (~0ULL << (b + 1));
                    avail = ~r[k] & vbits[w0 + k] & gt;
                }
            }
            cnt = c;
        } else if (t >= 512 && ch + 1 < NCHUNK) {
            // concurrently prefetch next chunk's diagonal block
            const int w0n = (ch + 1) * CHW;
            const int nwn = (NW - w0n < CHW) ? (NW - w0n) : CHW;
            unsigned long long* nbuf = diagbuf + ((ch + 1) & 1) * DIAGSZ;
            for (int idx = t - 512; idx < nwn * 64 * CHW; idx += 512) {
                int rr = idx / CHW, k = idx - rr * CHW;
                int gi = w0n * 64 + rr;
                nbuf[idx] = (k < nwn && gi < NTOP)
                          ? g_mask[(size_t)gi * NW + w0n + k] : 0ULL;
            }
        }
        __syncthreads();
        if (cnt >= NOUT || w0 + nw >= NW) break;

        // rebuild remv for the NEXT chunk's 8 words from ALL keeps so far
        if (t < CHW) nrem8[t] = 0ULL;
        __syncthreads();
        {
            int w = t & (CHW - 1);
            int gw = (ch + 1) * CHW + w;
            if (gw < NW) {
                unsigned long long acc = 0;
                for (int q = t >> 3; q < cnt; q += NTHR / CHW)
                    acc |= g_mask[(size_t)kept[q] * NW + gw];
                if (acc) atomicOr(&nrem8[w], acc);
            }
        }
        __syncthreads();
        if (t < CHW) remv8[t] = nrem8[t];
        __syncthreads();
    }
    __syncthreads();

    int c = cnt;
    const float inv = 0.0009765625f;   // 1/1024
    for (int o = t; o < NOUT; o += NTHR) {
        float4 bo = make_float4(0.f, 0.f, 0.f, 0.f);
        if (o < c) {
            float4 bb = g_tbox[kept[o]];
            bo.x = bb.x * inv; bo.y = bb.y * inv;
            bo.z = bb.z * inv; bo.w = bb.w * inv;
        }
        out[o * 4 + 0] = bo.x;
        out[o * 4 + 1] = bo.y;
        out[o * 4 + 2] = bo.z;
        out[o * 4 + 3] = bo.w;
    }
}

// ---------------- launch ------------------------------------------------------
extern "C" void kernel_launch(void* const* d_in, const int* in_sizes, int n_in,
                              void* d_out, int out_size) {
    const float* scores = (const float*)d_in[0];
    const float* deltas = (const float*)d_in[1];
    if (in_sizes[0] != 73728) {
        scores = (const float*)d_in[1];
        deltas = (const float*)d_in[0];
    }
    float* out = (float*)d_out;

    static bool attr_set = false;
    if (!attr_set) {
        cudaFuncSetAttribute(fused_kernel,
                             cudaFuncAttributeMaxDynamicSharedMemorySize,
                             2 * DIAGSZ * sizeof(unsigned long long));
        attr_set = true;
    }

    fused_kernel<<<NBLK, NTHR, 2 * DIAGSZ * sizeof(unsigned long long)>>>(
        scores, deltas, out);
}